// round 16
// baseline (speedup 1.0000x reference)
#include <cuda_runtime.h>
#include <math.h>

#define N_NODES   100000
#define N_EDGES   1600000
#define N_GRAPHS  64
#define IN_FEATS  64
#define HIDDEN    32
#define OUT_DIM   2
#define E4        (N_EDGES / 4)
#define NWARPS    ((N_NODES + 31) / 32)          // 3125 node-chunk warps
#define NF_BLOCKS ((NWARPS + 7) / 8)             // 391 (8 warps/block)
#define PGRID     1184                           // 148 SMs x 8 blocks: one wave

// Scratch (device globals — no allocation allowed)
__device__ __align__(16) float g_y2 [N_NODES * 2];   // y = nf @ W123   (float2 rows)
__device__ __align__(16) float g_z  [N_NODES * 4];   // z1 = [0:2N), z2 = [2N:4N)
__device__ __align__(16) float g_gsum[N_GRAPHS * IN_FEATS];
__device__ __align__(16) float g_gcnt[N_GRAPHS];
__device__ __align__(8) float g_cA[OUT_DIM];         // b1@W2@W3
__device__ __align__(8) float g_cB[OUT_DIM];         // b2@W3
__device__ __align__(8) float g_c0[OUT_DIM] = {0.f, 0.f};

#define NZ4  (N_NODES)                    // g_z in float4s (4N floats)
#define NO4  (N_NODES / 2)                // out h3 region in float4s (2N floats)
#define FILL_ITEMS  (NZ4 + NO4)
#define FILL_BLOCKS ((FILL_ITEMS + 255) / 256)    // 586

// Tiny: zero gsum/gcnt (must precede k_main's atomics)
__global__ void k_zsmall(float4* __restrict__ gsum, float4* __restrict__ gcnt) {
    int i = blockIdx.x * blockDim.x + threadIdx.x;
    const float4 zero = make_float4(0.f, 0.f, 0.f, 0.f);
    if (i < N_GRAPHS * IN_FEATS / 4) { gsum[i] = zero; return; }
    i -= N_GRAPHS * IN_FEATS / 4;
    if (i < N_GRAPHS / 4) gcnt[i] = zero;
}

// Merged kernel:
//  blocks [0, NF_BLOCKS)          : fused nf pass (local W123 fold; y2 + gsum/gcnt)
//  blocks [NF_BLOCKS, +FILL_BLOCKS): zero z, seed out h3 region with b3
__global__ void k_main(const float* __restrict__ nf, const int* __restrict__ gid,
                       const float* __restrict__ W1, const float* __restrict__ b1,
                       const float* __restrict__ W2, const float* __restrict__ b2,
                       const float* __restrict__ W3, const float* __restrict__ b3,
                       float2* __restrict__ y2, float* __restrict__ gsum,
                       float* __restrict__ gcnt,
                       float4* __restrict__ z, float4* __restrict__ h3,
                       float* __restrict__ cA, float* __restrict__ cB) {
    if (blockIdx.x >= NF_BLOCKS) {
        // ---- fill part ----
        int i = (blockIdx.x - NF_BLOCKS) * blockDim.x + threadIdx.x;
        const float4 zero = make_float4(0.f, 0.f, 0.f, 0.f);
        if (i < NZ4) { z[i] = zero; return; }
        i -= NZ4;
        if (i < NO4) {
            float b0 = __ldg(b3 + 0), b1v = __ldg(b3 + 1);
            h3[i] = make_float4(b0, b1v, b0, b1v);
        }
        return;
    }

    // ---- nf part: local weight fold into smem ----
    __shared__ float W23[HIDDEN * OUT_DIM];
    __shared__ float Ws [IN_FEATS * OUT_DIM];
    int t = threadIdx.x;
    if (t < HIDDEN * OUT_DIM) {
        int i = t >> 1, j = t & 1;
        float s = 0.f;
        for (int k = 0; k < HIDDEN; k++) s += W2[i * HIDDEN + k] * W3[k * OUT_DIM + j];
        W23[t] = s;
    }
    __syncthreads();
    if (t < IN_FEATS * OUT_DIM) {
        int i = t >> 1, j = t & 1;
        float s = 0.f;
        for (int k = 0; k < HIDDEN; k++) s += W1[i * HIDDEN + k] * W23[k * OUT_DIM + j];
        Ws[t] = s;
    }
    // block 0 publishes the folded bias constants for the edge passes
    if (blockIdx.x == 0 && t < OUT_DIM) {
        float sa = 0.f, sb = 0.f;
        for (int k = 0; k < HIDDEN; k++) {
            sa += b1[k] * W23[k * OUT_DIM + t];
            sb += b2[k] * W3[k * OUT_DIM + t];
        }
        cA[t] = sa;
        cB[t] = sb;
    }
    __syncthreads();

    int warp = blockIdx.x * 8 + (t >> 5);
    int lane = t & 31;
    if (warp >= NWARPS) return;
    int n0 = warp * 32;
    int n1 = n0 + 32; if (n1 > N_NODES) n1 = N_NODES;

    float w0a = Ws[lane * 2 + 0],        w1a = Ws[lane * 2 + 1];
    float w0b = Ws[(lane + 32) * 2 + 0], w1b = Ws[(lane + 32) * 2 + 1];

    float acc0 = 0.f, acc1 = 0.f;   // per-lane running graph sums (feat l, l+32)
    float cnt  = 0.f;
    int curg = __ldg(gid + n0);

    for (int n = n0; n < n1; n++) {
        int g = __ldg(gid + n);
        if (g != curg) {
            atomicAdd(&gsum[curg * IN_FEATS + lane],      acc0);
            atomicAdd(&gsum[curg * IN_FEATS + 32 + lane], acc1);
            if (lane == 0) atomicAdd(&gcnt[curg], cnt);
            acc0 = acc1 = cnt = 0.f;
            curg = g;
        }
        const float* row = nf + (size_t)n * IN_FEATS;
        float a = __ldg(row + lane);
        float b = __ldg(row + 32 + lane);
        acc0 += a; acc1 += b; cnt += 1.f;
        float p0 = a * w0a + b * w0b;
        float p1 = a * w1a + b * w1b;
        #pragma unroll
        for (int off = 16; off > 0; off >>= 1) {
            p0 += __shfl_xor_sync(0xffffffffu, p0, off);
            p1 += __shfl_xor_sync(0xffffffffu, p1, off);
        }
        if (lane == 0) y2[n] = make_float2(p0, p1);
    }
    atomicAdd(&gsum[curg * IN_FEATS + lane],      acc0);
    atomicAdd(&gsum[curg * IN_FEATS + 32 + lane], acc1);
    if (lane == 0) atomicAdd(&gcnt[curg], cnt);
}

// vout[dst] += vin[src] + c   (float2 rows, RED.64/edge, groups of 4 edges,
// grid-stride over E4 groups; PGRID blocks = exactly one resident wave)
__global__ void __launch_bounds__(256, 8)
k_passv2(const float2* __restrict__ vin, float* __restrict__ vout,
         const float* __restrict__ cvec,
         const int* __restrict__ src, const int* __restrict__ dst) {
    float c0 = __ldg(cvec + 0), c1 = __ldg(cvec + 1);
    int stride = gridDim.x * blockDim.x;
    for (int t = blockIdx.x * blockDim.x + threadIdx.x; t < E4; t += stride) {
        int4 s = ((const int4*)src)[t];
        int4 d = ((const int4*)dst)[t];
        float2 v0 = vin[s.x];
        float2 v1 = vin[s.y];
        float2 v2 = vin[s.z];
        float2 v3 = vin[s.w];
        asm volatile("red.global.add.v2.f32 [%0], {%1, %2};"
                     :: "l"(vout + (size_t)d.x * 2), "f"(v0.x + c0), "f"(v0.y + c1) : "memory");
        asm volatile("red.global.add.v2.f32 [%0], {%1, %2};"
                     :: "l"(vout + (size_t)d.y * 2), "f"(v1.x + c0), "f"(v1.y + c1) : "memory");
        asm volatile("red.global.add.v2.f32 [%0], {%1, %2};"
                     :: "l"(vout + (size_t)d.z * 2), "f"(v2.x + c0), "f"(v2.y + c1) : "memory");
        asm volatile("red.global.add.v2.f32 [%0], {%1, %2};"
                     :: "l"(vout + (size_t)d.w * 2), "f"(v3.x + c0), "f"(v3.y + c1) : "memory");
    }
}

// out[g] = sigmoid( mean(nf over graph g) @ Wl + bl )
__global__ void k_pred(const float* __restrict__ Wl, const float* __restrict__ bl,
                       const float* __restrict__ gsum, const float* __restrict__ gcnt,
                       float* __restrict__ out) {
    int g = threadIdx.x;
    if (g >= N_GRAPHS) return;
    float cnt = gcnt[g]; if (cnt < 1.f) cnt = 1.f;
    float s = bl[0];
    #pragma unroll 8
    for (int f = 0; f < IN_FEATS; f++)
        s += (gsum[g * IN_FEATS + f] / cnt) * Wl[f];
    out[g] = 1.f / (1.f + expf(-s));
}

extern "C" void kernel_launch(void* const* d_in, const int* in_sizes, int n_in,
                              void* d_out, int out_size) {
    const float* nf  = (const float*)d_in[0];
    // d_in[1] = edge_feats (unused by the reference model)
    const float* W1  = (const float*)d_in[2];
    const float* b1  = (const float*)d_in[3];
    const float* W2  = (const float*)d_in[4];
    const float* b2  = (const float*)d_in[5];
    const float* W3  = (const float*)d_in[6];
    const float* b3  = (const float*)d_in[7];
    const float* Wl  = (const float*)d_in[8];
    const float* bl  = (const float*)d_in[9];
    const int*   src = (const int*)d_in[10];
    const int*   dst = (const int*)d_in[11];
    const int*   gid = (const int*)d_in[12];
    float* out = (float*)d_out;

    float *p_y2, *p_z, *p_gsum, *p_gcnt, *p_cA, *p_cB, *p_c0;
    cudaGetSymbolAddress((void**)&p_y2,   g_y2);
    cudaGetSymbolAddress((void**)&p_z,    g_z);
    cudaGetSymbolAddress((void**)&p_gsum, g_gsum);
    cudaGetSymbolAddress((void**)&p_gcnt, g_gcnt);
    cudaGetSymbolAddress((void**)&p_cA,   g_cA);
    cudaGetSymbolAddress((void**)&p_cB,   g_cB);
    cudaGetSymbolAddress((void**)&p_c0,   g_c0);
    float* p_z1 = p_z;
    float* p_z2 = p_z + (size_t)N_NODES * 2;

    const int T = 256;

    // 1) zero gsum/gcnt (only dependency of k_main's atomics)
    k_zsmall<<<(N_GRAPHS * IN_FEATS / 4 + N_GRAPHS / 4 + T - 1) / T, T>>>(
        (float4*)p_gsum, (float4*)p_gcnt);

    // 2) merged: nf (local fold, y2/gsum/gcnt) + z zero + h3 seed, one launch
    k_main<<<NF_BLOCKS + FILL_BLOCKS, T>>>(
        nf, gid, W1, b1, W2, b2, W3, b3,
        (float2*)p_y2, p_gsum, p_gcnt,
        (float4*)p_z, (float4*)(out + N_GRAPHS), p_cA, p_cB);

    // 3) graph head (depends only on gsum/gcnt)
    k_pred<<<1, N_GRAPHS>>>(Wl, bl, p_gsum, p_gcnt, out);

    // 4) three 2-wide aggregation passes, single-wave grid-stride
    k_passv2<<<PGRID, T>>>((const float2*)p_y2, p_z1, p_c0, src, dst);
    k_passv2<<<PGRID, T>>>((const float2*)p_z1, p_z2, p_cA, src, dst);
    k_passv2<<<PGRID, T>>>((const float2*)p_z2, out + N_GRAPHS, p_cB, src, dst);
}

// round 17
// speedup vs baseline: 1.0267x; 1.0267x over previous
#include <cuda_runtime.h>
#include <math.h>

#define N_NODES   100000
#define N_EDGES   1600000
#define N_GRAPHS  64
#define IN_FEATS  64
#define HIDDEN    32
#define OUT_DIM   2
#define E4        (N_EDGES / 4)
#define E4B       ((E4 + 255) / 256)             // 1563 edge blocks
#define NWARPS    ((N_NODES + 31) / 32)          // 3125 node-chunk warps
#define NF_BLOCKS ((NWARPS + 7) / 8)             // 391 (8 warps/block)
#define NZ4       (N_NODES)                      // g_z in float4s (4N floats)
#define ZFB       ((NZ4 + 255) / 256)            // 391 z-fill blocks
#define NO4       (N_NODES / 2)                  // h3 region in float4s
#define HFB       ((NO4 + 255) / 256)            // 196 h3-seed blocks

// Scratch (device globals — no allocation allowed)
__device__ __align__(16) float g_y2 [N_NODES * 2];   // y = nf @ W123   (float2 rows)
__device__ __align__(16) float g_z  [N_NODES * 4];   // z1 = [0:2N), z2 = [2N:4N)
__device__ __align__(16) float g_gsum[N_GRAPHS * IN_FEATS];
__device__ __align__(16) float g_gcnt[N_GRAPHS];
__device__ __align__(8) float g_cA[OUT_DIM];         // b1@W2@W3
__device__ __align__(8) float g_cB[OUT_DIM];         // b2@W3
__device__ __align__(8) float g_c0[OUT_DIM] = {0.f, 0.f};

// Tiny: zero gsum/gcnt (the only state k_nf's atomics need; 1 block)
__global__ void k_zsmall(float4* __restrict__ gsum, float4* __restrict__ gcnt) {
    int i = threadIdx.x;
    const float4 zero = make_float4(0.f, 0.f, 0.f, 0.f);
    for (int j = i; j < N_GRAPHS * IN_FEATS / 4; j += 256) gsum[j] = zero;
    if (i < N_GRAPHS / 4) gcnt[i] = zero;
}

// blocks [0, NF_BLOCKS): fused nf pass (local W123 fold; y2 + gsum/gcnt; block 0
//                        publishes cA/cB)
// blocks [NF_BLOCKS, +ZFB): zero z (z1 and z2)
__global__ void k_nf(const float* __restrict__ nf, const int* __restrict__ gid,
                     const float* __restrict__ W1, const float* __restrict__ b1,
                     const float* __restrict__ W2, const float* __restrict__ b2,
                     const float* __restrict__ W3,
                     float2* __restrict__ y2, float* __restrict__ gsum,
                     float* __restrict__ gcnt, float4* __restrict__ z,
                     float* __restrict__ cA, float* __restrict__ cB) {
    if (blockIdx.x >= NF_BLOCKS) {
        int i = (blockIdx.x - NF_BLOCKS) * blockDim.x + threadIdx.x;
        if (i < NZ4) z[i] = make_float4(0.f, 0.f, 0.f, 0.f);
        return;
    }
    // ---- local weight fold into smem ----
    __shared__ float W23[HIDDEN * OUT_DIM];
    __shared__ float Ws [IN_FEATS * OUT_DIM];
    int t = threadIdx.x;
    if (t < HIDDEN * OUT_DIM) {
        int i = t >> 1, j = t & 1;
        float s = 0.f;
        for (int k = 0; k < HIDDEN; k++) s += W2[i * HIDDEN + k] * W3[k * OUT_DIM + j];
        W23[t] = s;
    }
    __syncthreads();
    if (t < IN_FEATS * OUT_DIM) {
        int i = t >> 1, j = t & 1;
        float s = 0.f;
        for (int k = 0; k < HIDDEN; k++) s += W1[i * HIDDEN + k] * W23[k * OUT_DIM + j];
        Ws[t] = s;
    }
    if (blockIdx.x == 0 && t < OUT_DIM) {
        float sa = 0.f, sb = 0.f;
        for (int k = 0; k < HIDDEN; k++) {
            sa += b1[k] * W23[k * OUT_DIM + t];
            sb += b2[k] * W3[k * OUT_DIM + t];
        }
        cA[t] = sa;
        cB[t] = sb;
    }
    __syncthreads();

    int warp = blockIdx.x * 8 + (t >> 5);
    int lane = t & 31;
    if (warp >= NWARPS) return;
    int n0 = warp * 32;
    int n1 = n0 + 32; if (n1 > N_NODES) n1 = N_NODES;

    float w0a = Ws[lane * 2 + 0],        w1a = Ws[lane * 2 + 1];
    float w0b = Ws[(lane + 32) * 2 + 0], w1b = Ws[(lane + 32) * 2 + 1];

    float acc0 = 0.f, acc1 = 0.f;   // per-lane running graph sums (feat l, l+32)
    float cnt  = 0.f;
    int curg = __ldg(gid + n0);

    for (int n = n0; n < n1; n++) {
        int g = __ldg(gid + n);
        if (g != curg) {
            atomicAdd(&gsum[curg * IN_FEATS + lane],      acc0);
            atomicAdd(&gsum[curg * IN_FEATS + 32 + lane], acc1);
            if (lane == 0) atomicAdd(&gcnt[curg], cnt);
            acc0 = acc1 = cnt = 0.f;
            curg = g;
        }
        const float* row = nf + (size_t)n * IN_FEATS;
        float a = __ldg(row + lane);
        float b = __ldg(row + 32 + lane);
        acc0 += a; acc1 += b; cnt += 1.f;
        float p0 = a * w0a + b * w0b;
        float p1 = a * w1a + b * w1b;
        #pragma unroll
        for (int off = 16; off > 0; off >>= 1) {
            p0 += __shfl_xor_sync(0xffffffffu, p0, off);
            p1 += __shfl_xor_sync(0xffffffffu, p1, off);
        }
        if (lane == 0) y2[n] = make_float2(p0, p1);
    }
    atomicAdd(&gsum[curg * IN_FEATS + lane],      acc0);
    atomicAdd(&gsum[curg * IN_FEATS + 32 + lane], acc1);
    if (lane == 0) atomicAdd(&gcnt[curg], cnt);
}

// Pass 1: z1[dst] += y2[src]  (4 edges/thread, R15 config) ;
// block E4B (appended) computes the graph prediction.
__global__ void k_pass1(const float2* __restrict__ vin, float* __restrict__ vout,
                        const int* __restrict__ src, const int* __restrict__ dst,
                        const float* __restrict__ Wl, const float* __restrict__ bl,
                        const float* __restrict__ gsum, const float* __restrict__ gcnt,
                        float* __restrict__ out) {
    if (blockIdx.x >= E4B) {
        int g = threadIdx.x;
        if (g >= N_GRAPHS) return;
        float cnt = gcnt[g]; if (cnt < 1.f) cnt = 1.f;
        float s = __ldg(bl);
        #pragma unroll 8
        for (int f = 0; f < IN_FEATS; f++)
            s += (gsum[g * IN_FEATS + f] / cnt) * __ldg(Wl + f);
        out[g] = 1.f / (1.f + expf(-s));
        return;
    }
    int t = blockIdx.x * blockDim.x + threadIdx.x;
    if (t >= E4) return;
    int4 s = ((const int4*)src)[t];
    int4 d = ((const int4*)dst)[t];
    float2 v0 = vin[s.x];
    float2 v1 = vin[s.y];
    float2 v2 = vin[s.z];
    float2 v3 = vin[s.w];
    asm volatile("red.global.add.v2.f32 [%0], {%1, %2};"
                 :: "l"(vout + (size_t)d.x * 2), "f"(v0.x), "f"(v0.y) : "memory");
    asm volatile("red.global.add.v2.f32 [%0], {%1, %2};"
                 :: "l"(vout + (size_t)d.y * 2), "f"(v1.x), "f"(v1.y) : "memory");
    asm volatile("red.global.add.v2.f32 [%0], {%1, %2};"
                 :: "l"(vout + (size_t)d.z * 2), "f"(v2.x), "f"(v2.y) : "memory");
    asm volatile("red.global.add.v2.f32 [%0], {%1, %2};"
                 :: "l"(vout + (size_t)d.w * 2), "f"(v3.x), "f"(v3.y) : "memory");
}

// Pass 2: z2[dst] += z1[src] + cA ; appended blocks seed out h3 region with b3
// (independent of the z2 REDs; must precede pass3 — satisfied by stream order).
__global__ void k_pass2(const float2* __restrict__ vin, float* __restrict__ vout,
                        const float* __restrict__ cvec,
                        const int* __restrict__ src, const int* __restrict__ dst,
                        float4* __restrict__ h3, const float* __restrict__ b3) {
    if (blockIdx.x >= E4B) {
        int i = (blockIdx.x - E4B) * blockDim.x + threadIdx.x;
        if (i < NO4) {
            float b0 = __ldg(b3 + 0), b1v = __ldg(b3 + 1);
            h3[i] = make_float4(b0, b1v, b0, b1v);
        }
        return;
    }
    int t = blockIdx.x * blockDim.x + threadIdx.x;
    if (t >= E4) return;
    float c0 = __ldg(cvec + 0), c1 = __ldg(cvec + 1);
    int4 s = ((const int4*)src)[t];
    int4 d = ((const int4*)dst)[t];
    float2 v0 = vin[s.x];
    float2 v1 = vin[s.y];
    float2 v2 = vin[s.z];
    float2 v3 = vin[s.w];
    asm volatile("red.global.add.v2.f32 [%0], {%1, %2};"
                 :: "l"(vout + (size_t)d.x * 2), "f"(v0.x + c0), "f"(v0.y + c1) : "memory");
    asm volatile("red.global.add.v2.f32 [%0], {%1, %2};"
                 :: "l"(vout + (size_t)d.y * 2), "f"(v1.x + c0), "f"(v1.y + c1) : "memory");
    asm volatile("red.global.add.v2.f32 [%0], {%1, %2};"
                 :: "l"(vout + (size_t)d.z * 2), "f"(v2.x + c0), "f"(v2.y + c1) : "memory");
    asm volatile("red.global.add.v2.f32 [%0], {%1, %2};"
                 :: "l"(vout + (size_t)d.w * 2), "f"(v3.x + c0), "f"(v3.y + c1) : "memory");
}

// Pass 3: out[64+2*dst] += z2[src] + cB  (plain)
__global__ void k_pass3(const float2* __restrict__ vin, float* __restrict__ vout,
                        const float* __restrict__ cvec,
                        const int* __restrict__ src, const int* __restrict__ dst) {
    int t = blockIdx.x * blockDim.x + threadIdx.x;
    if (t >= E4) return;
    float c0 = __ldg(cvec + 0), c1 = __ldg(cvec + 1);
    int4 s = ((const int4*)src)[t];
    int4 d = ((const int4*)dst)[t];
    float2 v0 = vin[s.x];
    float2 v1 = vin[s.y];
    float2 v2 = vin[s.z];
    float2 v3 = vin[s.w];
    asm volatile("red.global.add.v2.f32 [%0], {%1, %2};"
                 :: "l"(vout + (size_t)d.x * 2), "f"(v0.x + c0), "f"(v0.y + c1) : "memory");
    asm volatile("red.global.add.v2.f32 [%0], {%1, %2};"
                 :: "l"(vout + (size_t)d.y * 2), "f"(v1.x + c0), "f"(v1.y + c1) : "memory");
    asm volatile("red.global.add.v2.f32 [%0], {%1, %2};"
                 :: "l"(vout + (size_t)d.z * 2), "f"(v2.x + c0), "f"(v2.y + c1) : "memory");
    asm volatile("red.global.add.v2.f32 [%0], {%1, %2};"
                 :: "l"(vout + (size_t)d.w * 2), "f"(v3.x + c0), "f"(v3.y + c1) : "memory");
}

extern "C" void kernel_launch(void* const* d_in, const int* in_sizes, int n_in,
                              void* d_out, int out_size) {
    const float* nf  = (const float*)d_in[0];
    // d_in[1] = edge_feats (unused by the reference model)
    const float* W1  = (const float*)d_in[2];
    const float* b1  = (const float*)d_in[3];
    const float* W2  = (const float*)d_in[4];
    const float* b2  = (const float*)d_in[5];
    const float* W3  = (const float*)d_in[6];
    const float* b3  = (const float*)d_in[7];
    const float* Wl  = (const float*)d_in[8];
    const float* bl  = (const float*)d_in[9];
    const int*   src = (const int*)d_in[10];
    const int*   dst = (const int*)d_in[11];
    const int*   gid = (const int*)d_in[12];
    float* out = (float*)d_out;

    float *p_y2, *p_z, *p_gsum, *p_gcnt, *p_cA, *p_cB;
    cudaGetSymbolAddress((void**)&p_y2,   g_y2);
    cudaGetSymbolAddress((void**)&p_z,    g_z);
    cudaGetSymbolAddress((void**)&p_gsum, g_gsum);
    cudaGetSymbolAddress((void**)&p_gcnt, g_gcnt);
    cudaGetSymbolAddress((void**)&p_cA,   g_cA);
    cudaGetSymbolAddress((void**)&p_cB,   g_cB);
    float* p_z1 = p_z;
    float* p_z2 = p_z + (size_t)N_NODES * 2;

    const int T = 256;

    // 1) zero gsum/gcnt (only state k_nf's atomics require)
    k_zsmall<<<1, T>>>((float4*)p_gsum, (float4*)p_gcnt);

    // 2) nf pass (+ z1/z2 zero in appended blocks; fold published by block 0)
    k_nf<<<NF_BLOCKS + ZFB, T>>>(nf, gid, W1, b1, W2, b2, W3,
                                 (float2*)p_y2, p_gsum, p_gcnt,
                                 (float4*)p_z, p_cA, p_cB);

    // 3) pass1 (+ graph-prediction block appended)
    k_pass1<<<E4B + 1, T>>>((const float2*)p_y2, p_z1, src, dst,
                            Wl, bl, p_gsum, p_gcnt, out);

    // 4) pass2 (+ h3 b3-seed blocks appended; seed precedes pass3 by stream order)
    k_pass2<<<E4B + HFB, T>>>((const float2*)p_z1, p_z2, p_cA, src, dst,
                              (float4*)(out + N_GRAPHS), b3);

    // 5) pass3
    k_pass3<<<E4B, T>>>((const float2*)p_z2, out + N_GRAPHS, p_cB, src, dst);
}